// round 8
// baseline (speedup 1.0000x reference)
#include <cuda_runtime.h>
#include <math.h>

// ---------------- problem constants ----------------
#define NB      4
#define SEQL    513          // L = 512 tokens + cls
#define NTOK    (NB*SEQL)    // 2052
#define DMODEL  384
#define DI      768
#define NST     16
#define XD      56           // DTR + 2N
#define DTRC    24
#define DEPTH   8
#define NCH     16           // scan time chunks
#define CLEN    33           // chunk length (16*33 = 528 >= 513)
#define HEADD   256

typedef unsigned long long ull;

// ---------------- scratch (ONE static device struct, no allocs) ----------------
struct Scratch {
    float patch[2048*256];
    float h    [NTOK*DMODEL];
    float hn   [NTOK*DMODEL];
    float xz   [NTOK*2*DI];
    float xc   [NTOK*DI];
    float xdbl [NTOK*XD];
    float xdblp[4*NTOK*XD];
    float dt   [NTOK*DI];
    float y    [NTOK*DI];
    float A    [DEPTH*DI*NST];
    float send [NB*NCH*DI*NST];
    float aprod[NB*NCH*DI*NST];
    float sinit[NB*NCH*DI*NST];
    float part [2*NTOK*2*DI];         // split-K partials (max: in_proj 2 x 2052 x 1536)
};
__device__ Scratch g_s;

// ---------------- small helpers ----------------
__device__ __forceinline__ float silu_f(float x) {
    return x / (1.f + __expf(-x));
}
__device__ __forceinline__ ull dup_f32x2(float x) {
    ull r;
    asm("mov.b64 %0, {%1, %1};" : "=l"(r) : "f"(x));
    return r;
}
__device__ __forceinline__ void fma_f32x2(ull& acc, ull a, ull b) {
    asm("fma.rn.f32x2 %0, %1, %2, %0;" : "+l"(acc) : "l"(a), "l"(b));
}
union U64F2 { ull u; float2 f; };

// ---------------- A = -exp(A_log), once per launch ----------------
__global__ void __launch_bounds__(256) prep_A_kernel(const float* __restrict__ Alog) {
    int i = blockIdx.x*256 + threadIdx.x;
    if (i < DEPTH*DI*NST) g_s.A[i] = -__expf(Alog[i]);
}

// ---------------- patch reorder: x (B,T,F) -> patch rows (B*512, 256) ----------------
__global__ void __launch_bounds__(256) patch_reorder_kernel(const float* __restrict__ x) {
    int idx = blockIdx.x*256 + threadIdx.x;     // over 4*1024*128
    if (idx >= NB*1024*128) return;
    int f = idx & 127;
    int r = (idx >> 7) & 1023;                  // t index in [0,1024)
    int b = idx >> 17;
    g_s.patch[(((size_t)b*512 + (r>>1)) << 8) + f*2 + (r & 1)] = x[idx];
}

// ---------------- cls row: h[b,0,:] = cls + pos[0] ----------------
__global__ void __launch_bounds__(384) cls_kernel(const float* __restrict__ cls,
                                                  const float* __restrict__ pos) {
    int b = blockIdx.x;
    int d = threadIdx.x;     // 384
    g_s.h[(size_t)b*SEQL*DMODEL + d] = cls[d] + pos[d];
}

// ---------------- LayerNorm: row-per-block, D=384, 128 threads ----------------
__global__ void __launch_bounds__(128) ln_kernel(const float* __restrict__ in,
                          const float* __restrict__ w,
                          const float* __restrict__ bv,
                          float* __restrict__ out) {
    int row = blockIdx.x;
    int tid = threadIdx.x;
    const float* x = in + (size_t)row*DMODEL;
    float v0 = x[tid], v1 = x[tid+128], v2 = x[tid+256];
    float s = v0+v1+v2;
    float q = v0*v0 + v1*v1 + v2*v2;
    #pragma unroll
    for (int o = 16; o > 0; o >>= 1) {
        s += __shfl_xor_sync(0xFFFFFFFFu, s, o);
        q += __shfl_xor_sync(0xFFFFFFFFu, q, o);
    }
    __shared__ float ss[4], qq[4];
    if ((tid & 31) == 0) { ss[tid>>5] = s; qq[tid>>5] = q; }
    __syncthreads();
    s = ss[0]+ss[1]+ss[2]+ss[3];
    q = qq[0]+qq[1]+qq[2]+qq[3];
    float mean = s * (1.f/384.f);
    float var  = q * (1.f/384.f) - mean*mean;
    float inv  = rsqrtf(var + 1e-5f);
    float* o = out + (size_t)row*DMODEL;
    o[tid]     = (v0-mean)*inv*w[tid]     + bv[tid];
    o[tid+128] = (v1-mean)*inv*w[tid+128] + bv[tid+128];
    o[tid+256] = (v2-mean)*inv*w[tid+256] + bv[tid+256];
}

// ================= f32x2 GEMM: C[m,n] = sum_k A[m,k]*W[n,k] =================
// BM=128, BN=64, BK=16, 128 threads, 8x8 microtile via packed f32x2.
// Requirements: N % 64 == 0, (K per split) % 16 == 0. M arbitrary (guarded).
// KSPLIT: gridDim.z splits K evenly; partial z writes to C + z*M*ldc.
template<bool KSPLIT>
__global__ void __launch_bounds__(128, 3)
gemm2(const float* __restrict__ A, int lda,
      const float* __restrict__ W, int ldw,
      float* __restrict__ C, int ldc,
      int M, int N, int K)
{
    __shared__ float As[2][16][132];
    __shared__ float Ws[2][16][68];

    int tid = threadIdx.x;            // 128
    int tx = tid & 7;                 // n: 8 threads x 8 cols
    int ty = tid >> 3;                // m: 16 threads x 8 rows
    int m0 = blockIdx.x * 128;
    int n0 = blockIdx.y * 64;

    int kz0 = 0, ktiles = K >> 4;
    if (KSPLIT) {
        int klen = K / gridDim.z;     // multiple of 16 by construction
        kz0 = blockIdx.z * klen;
        ktiles = klen >> 4;
        C += (size_t)blockIdx.z * (size_t)M * ldc;
    }

    // accumulators: 4 m-pairs x 8 n, packed f32x2 (pair = adjacent m)
    ull acc[4][8];
    #pragma unroll
    for (int p = 0; p < 4; p++)
        #pragma unroll
        for (int n = 0; n < 8; n++) acc[p][n] = 0ull;

    // global-load staging registers
    float4 ra[4];                      // A: row (m0+tid), 16 k values
    float4 rb[2];                      // B: row (n0+(tid>>1)), 8 k values
    int arow = m0 + tid;
    const float* Aptr = A + (size_t)arow*lda + kz0;
    bool aval = (arow < M);
    int brow = tid >> 1;
    int bkh  = (tid & 1) * 8;
    const float* Bptr = W + (size_t)(n0 + brow)*ldw + kz0 + bkh;

    // prefetch tile 0
    {
        if (aval) {
            ra[0] = *(const float4*)(Aptr + 0);
            ra[1] = *(const float4*)(Aptr + 4);
            ra[2] = *(const float4*)(Aptr + 8);
            ra[3] = *(const float4*)(Aptr + 12);
        } else {
            ra[0]=ra[1]=ra[2]=ra[3]=make_float4(0,0,0,0);
        }
        rb[0] = *(const float4*)(Bptr + 0);
        rb[1] = *(const float4*)(Bptr + 4);
    }
    // store tile 0 to buf 0
    {
        #pragma unroll
        for (int q = 0; q < 4; q++) {
            As[0][q*4+0][tid] = (&ra[q].x)[0];
            As[0][q*4+1][tid] = (&ra[q].x)[1];
            As[0][q*4+2][tid] = (&ra[q].x)[2];
            As[0][q*4+3][tid] = (&ra[q].x)[3];
        }
        #pragma unroll
        for (int q = 0; q < 2; q++) {
            Ws[0][bkh+q*4+0][brow] = (&rb[q].x)[0];
            Ws[0][bkh+q*4+1][brow] = (&rb[q].x)[1];
            Ws[0][bkh+q*4+2][brow] = (&rb[q].x)[2];
            Ws[0][bkh+q*4+3][brow] = (&rb[q].x)[3];
        }
    }
    __syncthreads();

    for (int t = 0; t < ktiles; t++) {
        int buf = t & 1;
        // prefetch next tile into regs
        if (t + 1 < ktiles) {
            const float* Ap = Aptr + (t+1)*16;
            if (aval) {
                ra[0] = *(const float4*)(Ap + 0);
                ra[1] = *(const float4*)(Ap + 4);
                ra[2] = *(const float4*)(Ap + 8);
                ra[3] = *(const float4*)(Ap + 12);
            }
            const float* Bp = Bptr + (t+1)*16;
            rb[0] = *(const float4*)(Bp + 0);
            rb[1] = *(const float4*)(Bp + 4);
        }
        // compute on current buffer
        #pragma unroll
        for (int kk = 0; kk < 16; kk++) {
            const float* Ar = &As[buf][kk][ty*8];
            ulonglong2 a01 = *(const ulonglong2*)(Ar);
            ulonglong2 a23 = *(const ulonglong2*)(Ar + 4);
            float4 b0 = *(const float4*)&Ws[buf][kk][tx*8];
            float4 b1 = *(const float4*)&Ws[buf][kk][tx*8 + 4];
            ull bd[8];
            bd[0]=dup_f32x2(b0.x); bd[1]=dup_f32x2(b0.y);
            bd[2]=dup_f32x2(b0.z); bd[3]=dup_f32x2(b0.w);
            bd[4]=dup_f32x2(b1.x); bd[5]=dup_f32x2(b1.y);
            bd[6]=dup_f32x2(b1.z); bd[7]=dup_f32x2(b1.w);
            ull ap[4] = {a01.x, a01.y, a23.x, a23.y};
            #pragma unroll
            for (int p = 0; p < 4; p++)
                #pragma unroll
                for (int n = 0; n < 8; n++)
                    fma_f32x2(acc[p][n], ap[p], bd[n]);
        }
        __syncthreads();
        // store next tile
        if (t + 1 < ktiles) {
            int nb = (t+1) & 1;
            #pragma unroll
            for (int q = 0; q < 4; q++) {
                As[nb][q*4+0][tid] = aval ? (&ra[q].x)[0] : 0.f;
                As[nb][q*4+1][tid] = aval ? (&ra[q].x)[1] : 0.f;
                As[nb][q*4+2][tid] = aval ? (&ra[q].x)[2] : 0.f;
                As[nb][q*4+3][tid] = aval ? (&ra[q].x)[3] : 0.f;
            }
            #pragma unroll
            for (int q = 0; q < 2; q++) {
                Ws[nb][bkh+q*4+0][brow] = (&rb[q].x)[0];
                Ws[nb][bkh+q*4+1][brow] = (&rb[q].x)[1];
                Ws[nb][bkh+q*4+2][brow] = (&rb[q].x)[2];
                Ws[nb][bkh+q*4+3][brow] = (&rb[q].x)[3];
            }
            __syncthreads();
        }
    }

    // epilogue: unpack pairs, write with M guard
    #pragma unroll
    for (int p = 0; p < 4; p++) {
        int m_lo = m0 + ty*8 + 2*p;
        if (m_lo >= M) continue;
        bool hi_ok = (m_lo + 1 < M);
        float* Cl = C + (size_t)m_lo*ldc + n0 + tx*8;
        float* Ch = Cl + ldc;
        #pragma unroll
        for (int n = 0; n < 8; n++) {
            U64F2 u; u.u = acc[p][n];
            Cl[n] = u.f.x;
            if (hi_ok) Ch[n] = u.f.y;
        }
    }
}

// ---------------- split-K reduce variants (P partial buffers) ----------------
template<int P>
__global__ void __launch_bounds__(256) reduce_sum(const float* __restrict__ part,
                                                  float* __restrict__ outp, int MN) {
    int i = blockIdx.x*256 + threadIdx.x;
    if (i < MN) {
        float v = 0.f;
        #pragma unroll
        for (int p = 0; p < P; p++) v += part[i + (size_t)p*MN];
        outp[i] = v;
    }
}
template<int P>
__global__ void __launch_bounds__(256) reduce_res(const float* __restrict__ part,
                                                  float* __restrict__ h, int MN) {
    int i = blockIdx.x*256 + threadIdx.x;
    if (i < MN) {
        float v = 0.f;
        #pragma unroll
        for (int p = 0; p < P; p++) v += part[i + (size_t)p*MN];
        h[i] += v;
    }
}
template<int P>
__global__ void __launch_bounds__(256) reduce_relu(const float* __restrict__ part,
                                                   const float* __restrict__ bias,
                                                   float* __restrict__ outp, int MN, int ldn) {
    int i = blockIdx.x*256 + threadIdx.x;
    if (i < MN) {
        float v = bias[i % ldn];
        #pragma unroll
        for (int p = 0; p < P; p++) v += part[i + (size_t)p*MN];
        outp[i] = fmaxf(v, 0.f);
    }
}
template<int P>
__global__ void __launch_bounds__(256) reduce_bias(const float* __restrict__ part,
                                                   const float* __restrict__ bias,
                                                   float* __restrict__ outp, int MN, int ldn) {
    int i = blockIdx.x*256 + threadIdx.x;
    if (i < MN) {
        float v = bias[i % ldn];
        #pragma unroll
        for (int p = 0; p < P; p++) v += part[i + (size_t)p*MN];
        outp[i] = v;
    }
}
// patch: M=2048 rows x 384; scatter to h rows (skip cls), add bias + pos
template<int P>
__global__ void __launch_bounds__(256) reduce_patch(const float* __restrict__ part,
                                                    const float* __restrict__ bias,
                                                    const float* __restrict__ pos) {
    int i = blockIdx.x*256 + threadIdx.x;
    const int MN = 2048*DMODEL;
    if (i >= MN) return;
    int n = i % DMODEL;
    int m = i / DMODEL;
    float v = bias[n] + pos[(size_t)((m & 511) + 1)*DMODEL + n];
    #pragma unroll
    for (int p = 0; p < P; p++) v += part[i + (size_t)p*MN];
    int rout = m + (m >> 9) + 1;          // b*513 + 1 + t
    g_s.h[(size_t)rout*DMODEL + n] = v;
}

// ---------------- old generic NT GEMM (kept for xproj / dt) ----------------
enum { E_NONE=0, E_SP=3 };

template<int EPI, bool VEC, bool KSPLIT>
__global__ void __launch_bounds__(256)
gemm_nt(const float* __restrict__ A, int lda,
        const float* __restrict__ W, int ldw,
        const float* __restrict__ bias,
        float* __restrict__ C, int ldc,
        int M, int N, int K)
{
    constexpr int BM = 64, BN = 64, BK = 16;
    __shared__ float As[BK][BM+4];
    __shared__ float Ws[BK][BN+4];
    int tid = threadIdx.x;                 // 256
    int m0 = blockIdx.x*BM, n0 = blockIdx.y*BN;
    int kz0 = 0, kz1 = K;
    if (KSPLIT) {
        int klen = (K + gridDim.z - 1) / gridDim.z;
        kz0 = blockIdx.z * klen;
        kz1 = min(K, kz0 + klen);
        C += (size_t)blockIdx.z * (size_t)M * ldc;
    }
    float acc[4][4];
    #pragma unroll
    for (int i = 0; i < 4; i++)
        #pragma unroll
        for (int j = 0; j < 4; j++) acc[i][j] = 0.f;

    int lr  = tid >> 2;
    int lc4 = (tid & 3) * 4;
    int ty  = tid >> 4, tx = tid & 15;

    for (int k0 = kz0; k0 < kz1; k0 += BK) {
        int ma = m0 + lr;
        int na = n0 + lr;
        if (VEC) {
            float4 va = make_float4(0,0,0,0), vw = make_float4(0,0,0,0);
            if (ma < M && (k0+lc4) < kz1) va = *(const float4*)(A + (size_t)ma*lda + k0 + lc4);
            if (na < N && (k0+lc4) < kz1) vw = *(const float4*)(W + (size_t)na*ldw + k0 + lc4);
            As[lc4+0][lr]=va.x; As[lc4+1][lr]=va.y; As[lc4+2][lr]=va.z; As[lc4+3][lr]=va.w;
            Ws[lc4+0][lr]=vw.x; Ws[lc4+1][lr]=vw.y; Ws[lc4+2][lr]=vw.z; Ws[lc4+3][lr]=vw.w;
        } else {
            #pragma unroll
            for (int j = 0; j < 4; j++) {
                int k = k0 + lc4 + j;
                As[lc4+j][lr] = (ma < M && k < kz1) ? A[(size_t)ma*lda + k] : 0.f;
                Ws[lc4+j][lr] = (na < N && k < kz1) ? W[(size_t)na*ldw + k] : 0.f;
            }
        }
        __syncthreads();
        #pragma unroll
        for (int kk = 0; kk < BK; kk++) {
            float a[4], bb[4];
            #pragma unroll
            for (int i = 0; i < 4; i++) a[i]  = As[kk][ty*4 + i];
            #pragma unroll
            for (int j = 0; j < 4; j++) bb[j] = Ws[kk][tx*4 + j];
            #pragma unroll
            for (int i = 0; i < 4; i++)
                #pragma unroll
                for (int j = 0; j < 4; j++)
                    acc[i][j] = fmaf(a[i], bb[j], acc[i][j]);
        }
        __syncthreads();
    }

    #pragma unroll
    for (int i = 0; i < 4; i++) {
        int m = m0 + ty*4 + i;
        if (m >= M) continue;
        #pragma unroll
        for (int j = 0; j < 4; j++) {
            int n = n0 + tx*4 + j;
            if (n >= N) continue;
            float v = acc[i][j];
            if (EPI == E_SP) { v += bias[n]; v = (v > 15.f) ? v : log1pf(__expf(v)); }
            C[(size_t)m*ldc + n] = v;
        }
    }
}

// ---------------- causal depthwise conv1d (K=4) + silu ----------------
__global__ void __launch_bounds__(256) conv1d_kernel(const float* __restrict__ w,
                                                     const float* __restrict__ bias) {
    int idx = blockIdx.x*256 + threadIdx.x;
    if (idx >= NTOK*DI) return;
    int d  = idx % DI;
    int bt = idx / DI;
    int b  = bt / SEQL;
    int t  = bt - b*SEQL;
    float acc = bias[d];
    const float* w4 = w + (size_t)d*4;
    #pragma unroll
    for (int k = 0; k < 4; k++) {
        int tt = t - 3 + k;
        if (tt >= 0)
            acc = fmaf(w4[k], g_s.xz[(size_t)(b*SEQL + tt)*(2*DI) + d], acc);
    }
    g_s.xc[idx] = silu_f(acc);
}

// ---------------- split-K reduce for x_proj ----------------
__global__ void __launch_bounds__(256) reduce_xdbl_kernel() {
    int i = blockIdx.x*256 + threadIdx.x;
    if (i < NTOK*XD) {
        const int PS = NTOK*XD;
        g_s.xdbl[i] = (g_s.xdblp[i] + g_s.xdblp[i+PS])
                    + (g_s.xdblp[i+2*PS] + g_s.xdblp[i+3*PS]);
    }
}

// ---------------- selective scan: 3-pass blocked scan ----------------
__global__ void __launch_bounds__(128) scan_pass1(const float* __restrict__ Aoff) {
    int d = blockIdx.x*128 + threadIdx.x;
    int c = blockIdx.y, b = blockIdx.z;
    float s[NST], ap[NST], Av[NST];
    const float4* A4 = (const float4*)(Aoff + (size_t)d*NST);
    #pragma unroll
    for (int i = 0; i < 4; i++) {
        float4 v = A4[i];
        Av[4*i]=v.x; Av[4*i+1]=v.y; Av[4*i+2]=v.z; Av[4*i+3]=v.w;
    }
    #pragma unroll
    for (int n = 0; n < NST; n++) { s[n] = 0.f; ap[n] = 1.f; }
    int t0 = c*CLEN, t1 = min(t0 + CLEN, SEQL);
    for (int t = t0; t < t1; t++) {
        int bt = b*SEQL + t;
        float dtv = g_s.dt[(size_t)bt*DI + d];
        float xcv = g_s.xc[(size_t)bt*DI + d];
        float du  = dtv * xcv;
        const float4* Bp = (const float4*)(g_s.xdbl + (size_t)bt*XD + DTRC);
        float Bv[NST];
        #pragma unroll
        for (int i = 0; i < 4; i++) {
            float4 v = Bp[i];
            Bv[4*i]=v.x; Bv[4*i+1]=v.y; Bv[4*i+2]=v.z; Bv[4*i+3]=v.w;
        }
        #pragma unroll
        for (int n = 0; n < NST; n++) {
            float e = __expf(dtv * Av[n]);
            ap[n] *= e;
            s[n] = fmaf(e, s[n], du * Bv[n]);
        }
    }
    size_t base = (((size_t)b*NCH + c)*DI + d) * NST;
    float4* se  = (float4*)(g_s.send  + base);
    float4* apo = (float4*)(g_s.aprod + base);
    #pragma unroll
    for (int i = 0; i < 4; i++) {
        se[i]  = make_float4(s[4*i],  s[4*i+1],  s[4*i+2],  s[4*i+3]);
        apo[i] = make_float4(ap[4*i], ap[4*i+1], ap[4*i+2], ap[4*i+3]);
    }
}

__global__ void __launch_bounds__(256) scan_pass2() {
    int idx = blockIdx.x*256 + threadIdx.x;
    if (idx >= NB*DI*NST) return;
    int b  = idx / (DI*NST);
    int dn = idx - b*DI*NST;
    float s = 0.f;
    #pragma unroll
    for (int c = 0; c < NCH; c++) {
        size_t o = ((size_t)b*NCH + c)*DI*NST + dn;
        g_s.sinit[o] = s;
        s = fmaf(g_s.aprod[o], s, g_s.send[o]);
    }
}

__global__ void __launch_bounds__(128) scan_pass3(const float* __restrict__ Aoff,
                                                  const float* __restrict__ Dsk) {
    int d = blockIdx.x*128 + threadIdx.x;
    int c = blockIdx.y, b = blockIdx.z;
    float s[NST], Av[NST];
    const float4* A4 = (const float4*)(Aoff + (size_t)d*NST);
    #pragma unroll
    for (int i = 0; i < 4; i++) {
        float4 v = A4[i];
        Av[4*i]=v.x; Av[4*i+1]=v.y; Av[4*i+2]=v.z; Av[4*i+3]=v.w;
    }
    size_t base = (((size_t)b*NCH + c)*DI + d) * NST;
    const float4* si = (const float4*)(g_s.sinit + base);
    #pragma unroll
    for (int i = 0; i < 4; i++) {
        float4 v = si[i];
        s[4*i]=v.x; s[4*i+1]=v.y; s[4*i+2]=v.z; s[4*i+3]=v.w;
    }
    float Dv = Dsk[d];
    int t0 = c*CLEN, t1 = min(t0 + CLEN, SEQL);
    for (int t = t0; t < t1; t++) {
        int bt = b*SEQL + t;
        float dtv = g_s.dt[(size_t)bt*DI + d];
        float xcv = g_s.xc[(size_t)bt*DI + d];
        float du  = dtv * xcv;
        const float4* Bp = (const float4*)(g_s.xdbl + (size_t)bt*XD + DTRC);
        const float4* Cp = (const float4*)(g_s.xdbl + (size_t)bt*XD + DTRC + NST);
        float Bv[NST], Cv[NST];
        #pragma unroll
        for (int i = 0; i < 4; i++) {
            float4 v = Bp[i];
            Bv[4*i]=v.x; Bv[4*i+1]=v.y; Bv[4*i+2]=v.z; Bv[4*i+3]=v.w;
            float4 u = Cp[i];
            Cv[4*i]=u.x; Cv[4*i+1]=u.y; Cv[4*i+2]=u.z; Cv[4*i+3]=u.w;
        }
        float accy = 0.f;
        #pragma unroll
        for (int n = 0; n < NST; n++) {
            float e = __expf(dtv * Av[n]);
            s[n] = fmaf(e, s[n], du * Bv[n]);
            accy = fmaf(s[n], Cv[n], accy);
        }
        float zv = g_s.xz[(size_t)bt*(2*DI) + DI + d];
        g_s.y[(size_t)bt*DI + d] = (accy + Dv*xcv) * silu_f(zv);
    }
}

// ---------------- host launch ----------------
extern "C" void kernel_launch(void* const* d_in, const int* in_sizes, int n_in,
                              void* d_out, int out_size)
{
    (void)in_sizes; (void)n_in; (void)out_size;
    const float* x        = (const float*)d_in[0];
    const float* conv_w   = (const float*)d_in[1];
    const float* conv_b   = (const float*)d_in[2];
    const float* cls_tok  = (const float*)d_in[3];
    const float* pos      = (const float*)d_in[4];
    const float* norm_w   = (const float*)d_in[5];
    const float* norm_b   = (const float*)d_in[6];
    const float* in_proj  = (const float*)d_in[7];
    const float* c1w      = (const float*)d_in[8];
    const float* c1b      = (const float*)d_in[9];
    const float* xpw      = (const float*)d_in[10];
    const float* dtw      = (const float*)d_in[11];
    const float* dtb      = (const float*)d_in[12];
    const float* A_log    = (const float*)d_in[13];
    const float* D_skip   = (const float*)d_in[14];
    const float* opw      = (const float*)d_in[15];
    const float* normf_w  = (const float*)d_in[16];
    const float* normf_b  = (const float*)d_in[17];
    const float* hw1      = (const float*)d_in[18];
    const float* hb1      = (const float*)d_in[19];
    const float* hw2      = (const float*)d_in[20];
    const float* hb2      = (const float*)d_in[21];
    float* out = (float*)d_out;

    void* sp = nullptr;
    cudaGetSymbolAddress(&sp, g_s);
    Scratch* S = (Scratch*)sp;
    float* pPatch = S->patch;
    float* pH     = S->h;
    float* pHn    = S->hn;
    float* pXz    = S->xz;
    float* pXc    = S->xc;
    float* pXdbl  = S->xdbl;
    float* pXdblP = S->xdblp;
    float* pDt    = S->dt;
    float* pY     = S->y;
    float* pA     = S->A;
    float* pPart  = S->part;

    prep_A_kernel<<<(DEPTH*DI*NST + 255)/256, 256>>>(A_log);

    // patch embed: gemm2 splitK=4 (K=256 -> 64 each) + patch reduce (bias+pos+scatter)
    patch_reorder_kernel<<<(NB*1024*128 + 255)/256, 256>>>(x);
    cls_kernel<<<NB, DMODEL>>>(cls_tok, pos);
    gemm2<true><<<dim3(16, 6, 4), 128>>>(
        pPatch, 256, conv_w, 256, pPart, DMODEL, 2048, DMODEL, 256);
    reduce_patch<4><<<(2048*DMODEL + 255)/256, 256>>>(pPart, conv_b, pos);

    const int MT128 = (NTOK + 127)/128;   // 17
    const int MT64  = (NTOK + 63)/64;     // 33
    const int MNh   = NTOK*DMODEL;        // 788k
    const int MNxz  = NTOK*2*DI;          // 3.15M

    for (int l = 0; l < DEPTH; l++) {
        const float* nw   = norm_w + (size_t)l*DMODEL;
        const float* nb   = norm_b + (size_t)l*DMODEL;
        const float* ipw  = in_proj + (size_t)l*2*DI*DMODEL;
        const float* cw   = c1w + (size_t)l*DI*4;
        const float* cb   = c1b + (size_t)l*DI;
        const float* xp   = xpw + (size_t)l*XD*DI;
        const float* dw   = dtw + (size_t)l*DI*DTRC;
        const float* db   = dtb + (size_t)l*DI;
        const float* Aoff = pA  + (size_t)l*DI*NST;
        const float* Dsk  = D_skip + (size_t)l*DI;
        const float* ow   = opw + (size_t)l*DMODEL*DI;

        ln_kernel<<<NTOK, 128>>>(pH, nw, nb, pHn);

        // xz = hn @ in_proj^T   (2052 x 1536, K=384): splitK=2 -> grid 17x24x2=816
        gemm2<true><<<dim3(MT128, 24, 2), 128>>>(
            pHn, DMODEL, ipw, DMODEL, pPart, 2*DI, NTOK, 2*DI, DMODEL);
        reduce_sum<2><<<(MNxz + 255)/256, 256>>>(pPart, pXz, MNxz);

        conv1d_kernel<<<(NTOK*DI + 255)/256, 256>>>(cw, cb);

        // xdbl = xc @ x_proj^T  (2052 x 56, K=768) old kernel splitK=4
        gemm_nt<E_NONE, true, true><<<dim3(MT64, 1, 4), 256>>>(
            pXc, DI, xp, DI, nullptr, pXdblP, XD, NTOK, XD, DI);
        reduce_xdbl_kernel<<<(NTOK*XD + 255)/256, 256>>>();

        // dt = softplus(xdbl[:, :24] @ dt_proj^T + dtb)  (2052 x 768, K=24)
        gemm_nt<E_SP, false, false><<<dim3(MT64, 12), 256>>>(
            pXdbl, XD, dw, DTRC, db, pDt, DI, NTOK, DI, DTRC);

        // selective scan (3-pass blocked)
        scan_pass1<<<dim3(DI/128, NCH, NB), 128>>>(Aoff);
        scan_pass2<<<(NB*DI*NST + 255)/256, 256>>>();
        scan_pass3<<<dim3(DI/128, NCH, NB), 128>>>(Aoff, Dsk);

        // h += y @ out_proj^T   (2052 x 384, K=768): splitK=4 -> grid 408
        gemm2<true><<<dim3(MT128, 6, 4), 128>>>(
            pY, DI, ow, DI, pPart, DMODEL, NTOK, DMODEL, DI);
        reduce_res<4><<<(MNh + 255)/256, 256>>>(pPart, pH, MNh);
    }

    // final LN + head
    ln_kernel<<<NTOK, 128>>>(pH, normf_w, normf_b, pHn);

    // h1 = relu(hn @ hw1^T + hb1)  (2052 x 384, K=384): splitK=4 -> grid 408
    gemm2<true><<<dim3(MT128, 6, 4), 128>>>(
        pHn, DMODEL, hw1, DMODEL, pPart, DMODEL, NTOK, DMODEL, DMODEL);
    reduce_relu<4><<<(MNh + 255)/256, 256>>>(pPart, hb1, pXc, MNh, DMODEL);

    // out = h1 @ hw2^T + hb2       (2052 x 256, K=384): splitK=4 -> grid 272
    gemm2<true><<<dim3(MT128, 4, 4), 128>>>(
        pXc, DMODEL, hw2, DMODEL, pPart, HEADD, NTOK, HEADD, DMODEL);
    reduce_bias<4><<<(NTOK*HEADD + 255)/256, 256>>>(pPart, hb2, out, NTOK*HEADD, HEADD);
}

// round 9
// speedup vs baseline: 1.1313x; 1.1313x over previous
#include <cuda_runtime.h>
#include <math.h>

// ---------------- problem constants ----------------
#define NB      4
#define SEQL    513          // L = 512 tokens + cls
#define NTOK    (NB*SEQL)    // 2052
#define DMODEL  384
#define DI      768
#define NST     16
#define XD      56           // DTR + 2N
#define DTRC    24
#define DEPTH   8
#define NCH     16           // scan time chunks
#define CLEN    33           // chunk length (16*33 = 528 >= 513)
#define HEADD   256

// ---------------- scratch (ONE static device struct, no allocs) ----------------
struct Scratch {
    float patch[2048*256];
    float h    [NTOK*DMODEL];
    float hn   [NTOK*DMODEL];
    float xz   [NTOK*2*DI];
    float xc   [NTOK*DI];
    float xdbl [NTOK*XD];
    float xdblp[4*NTOK*XD];
    float dt   [NTOK*DI];
    float y    [NTOK*DI];
    float A    [DEPTH*DI*NST];
    float send [NB*NCH*DI*NST];
    float aprod[NB*NCH*DI*NST];
    float sinit[NB*NCH*DI*NST];
    float part [4*NTOK*DMODEL];       // split-K partials (max 4 x 2052 x 384)
};
__device__ Scratch g_s;

// ---------------- small helpers ----------------
__device__ __forceinline__ float silu_f(float x) {
    return x / (1.f + __expf(-x));
}

// ---------------- A = -exp(A_log), once per launch ----------------
__global__ void __launch_bounds__(256) prep_A_kernel(const float* __restrict__ Alog) {
    int i = blockIdx.x*256 + threadIdx.x;
    if (i < DEPTH*DI*NST) g_s.A[i] = -__expf(Alog[i]);
}

// ---------------- patch reorder: x (B,T,F) -> patch rows (B*512, 256) ----------------
__global__ void __launch_bounds__(256) patch_reorder_kernel(const float* __restrict__ x) {
    int idx = blockIdx.x*256 + threadIdx.x;     // over 4*1024*128
    if (idx >= NB*1024*128) return;
    int f = idx & 127;
    int r = (idx >> 7) & 1023;                  // t index in [0,1024)
    int b = idx >> 17;
    g_s.patch[(((size_t)b*512 + (r>>1)) << 8) + f*2 + (r & 1)] = x[idx];
}

// ---------------- cls row: h[b,0,:] = cls + pos[0] ----------------
__global__ void __launch_bounds__(384) cls_kernel(const float* __restrict__ cls,
                                                  const float* __restrict__ pos) {
    int b = blockIdx.x;
    int d = threadIdx.x;     // 384
    g_s.h[(size_t)b*SEQL*DMODEL + d] = cls[d] + pos[d];
}

// ---------------- LayerNorm: row-per-block, D=384, 128 threads ----------------
__global__ void __launch_bounds__(128) ln_kernel(const float* __restrict__ in,
                          const float* __restrict__ w,
                          const float* __restrict__ bv,
                          float* __restrict__ out) {
    int row = blockIdx.x;
    int tid = threadIdx.x;
    const float* x = in + (size_t)row*DMODEL;
    float v0 = x[tid], v1 = x[tid+128], v2 = x[tid+256];
    float s = v0+v1+v2;
    float q = v0*v0 + v1*v1 + v2*v2;
    #pragma unroll
    for (int o = 16; o > 0; o >>= 1) {
        s += __shfl_xor_sync(0xFFFFFFFFu, s, o);
        q += __shfl_xor_sync(0xFFFFFFFFu, q, o);
    }
    __shared__ float ss[4], qq[4];
    if ((tid & 31) == 0) { ss[tid>>5] = s; qq[tid>>5] = q; }
    __syncthreads();
    s = ss[0]+ss[1]+ss[2]+ss[3];
    q = qq[0]+qq[1]+qq[2]+qq[3];
    float mean = s * (1.f/384.f);
    float var  = q * (1.f/384.f) - mean*mean;
    float inv  = rsqrtf(var + 1e-5f);
    float* o = out + (size_t)row*DMODEL;
    o[tid]     = (v0-mean)*inv*w[tid]     + bv[tid];
    o[tid+128] = (v1-mean)*inv*w[tid+128] + bv[tid+128];
    o[tid+256] = (v2-mean)*inv*w[tid+256] + bv[tid+256];
}

// ================= scalar 8x8 GEMM: C[m,n] = sum_k A[m,k]*W[n,k] =================
// BM=128, BN=64, BK=16, 128 threads, 8x8 microtile, plain FFMA (sm_100a).
// Requirements: N % 64 == 0, (K per split) % 16 == 0. M arbitrary (guarded).
// KSPLIT: gridDim.z splits K evenly; partial z writes to C + z*M*ldc.
template<bool KSPLIT>
__global__ void __launch_bounds__(128, 4)
gemm2(const float* __restrict__ A, int lda,
      const float* __restrict__ W, int ldw,
      float* __restrict__ C, int ldc,
      int M, int N, int K)
{
    __shared__ float As[2][16][132];
    __shared__ float Ws[2][16][68];

    int tid = threadIdx.x;            // 128
    int tx = tid & 7;                 // n: 8 threads x 8 cols
    int ty = tid >> 3;                // m: 16 threads x 8 rows
    int m0 = blockIdx.x * 128;
    int n0 = blockIdx.y * 64;

    int kz0 = 0, ktiles = K >> 4;
    if (KSPLIT) {
        int klen = K / gridDim.z;     // multiple of 16 by construction
        kz0 = blockIdx.z * klen;
        ktiles = klen >> 4;
        C += (size_t)blockIdx.z * (size_t)M * ldc;
    }

    float acc[8][8];
    #pragma unroll
    for (int i = 0; i < 8; i++)
        #pragma unroll
        for (int j = 0; j < 8; j++) acc[i][j] = 0.f;

    // global-load staging registers
    float4 ra[4];                      // A: row (m0+tid), 16 k values
    float4 rb[2];                      // B: row (n0+(tid>>1)), 8 k values
    int arow = m0 + tid;
    const float* Aptr = A + (size_t)arow*lda + kz0;
    bool aval = (arow < M);
    int brow = tid >> 1;
    int bkh  = (tid & 1) * 8;
    const float* Bptr = W + (size_t)(n0 + brow)*ldw + kz0 + bkh;

    // prefetch tile 0
    if (aval) {
        ra[0] = *(const float4*)(Aptr + 0);
        ra[1] = *(const float4*)(Aptr + 4);
        ra[2] = *(const float4*)(Aptr + 8);
        ra[3] = *(const float4*)(Aptr + 12);
    } else {
        ra[0]=ra[1]=ra[2]=ra[3]=make_float4(0,0,0,0);
    }
    rb[0] = *(const float4*)(Bptr + 0);
    rb[1] = *(const float4*)(Bptr + 4);

    // store tile 0 to buf 0 (transposed k-major)
    #pragma unroll
    for (int q = 0; q < 4; q++) {
        As[0][q*4+0][tid] = (&ra[q].x)[0];
        As[0][q*4+1][tid] = (&ra[q].x)[1];
        As[0][q*4+2][tid] = (&ra[q].x)[2];
        As[0][q*4+3][tid] = (&ra[q].x)[3];
    }
    #pragma unroll
    for (int q = 0; q < 2; q++) {
        Ws[0][bkh+q*4+0][brow] = (&rb[q].x)[0];
        Ws[0][bkh+q*4+1][brow] = (&rb[q].x)[1];
        Ws[0][bkh+q*4+2][brow] = (&rb[q].x)[2];
        Ws[0][bkh+q*4+3][brow] = (&rb[q].x)[3];
    }
    __syncthreads();

    for (int t = 0; t < ktiles; t++) {
        int buf = t & 1;
        // prefetch next tile into regs
        if (t + 1 < ktiles) {
            const float* Ap = Aptr + (t+1)*16;
            if (aval) {
                ra[0] = *(const float4*)(Ap + 0);
                ra[1] = *(const float4*)(Ap + 4);
                ra[2] = *(const float4*)(Ap + 8);
                ra[3] = *(const float4*)(Ap + 12);
            }
            const float* Bp = Bptr + (t+1)*16;
            rb[0] = *(const float4*)(Bp + 0);
            rb[1] = *(const float4*)(Bp + 4);
        }
        // compute on current buffer
        #pragma unroll
        for (int kk = 0; kk < 16; kk++) {
            float af[8], bf[8];
            float4 a0 = *(const float4*)&As[buf][kk][ty*8];
            float4 a1 = *(const float4*)&As[buf][kk][ty*8 + 4];
            float4 b0 = *(const float4*)&Ws[buf][kk][tx*8];
            float4 b1 = *(const float4*)&Ws[buf][kk][tx*8 + 4];
            af[0]=a0.x; af[1]=a0.y; af[2]=a0.z; af[3]=a0.w;
            af[4]=a1.x; af[5]=a1.y; af[6]=a1.z; af[7]=a1.w;
            bf[0]=b0.x; bf[1]=b0.y; bf[2]=b0.z; bf[3]=b0.w;
            bf[4]=b1.x; bf[5]=b1.y; bf[6]=b1.z; bf[7]=b1.w;
            #pragma unroll
            for (int i = 0; i < 8; i++)
                #pragma unroll
                for (int j = 0; j < 8; j++)
                    acc[i][j] = fmaf(af[i], bf[j], acc[i][j]);
        }
        __syncthreads();
        // store next tile
        if (t + 1 < ktiles) {
            int nb = (t+1) & 1;
            #pragma unroll
            for (int q = 0; q < 4; q++) {
                As[nb][q*4+0][tid] = aval ? (&ra[q].x)[0] : 0.f;
                As[nb][q*4+1][tid] = aval ? (&ra[q].x)[1] : 0.f;
                As[nb][q*4+2][tid] = aval ? (&ra[q].x)[2] : 0.f;
                As[nb][q*4+3][tid] = aval ? (&ra[q].x)[3] : 0.f;
            }
            #pragma unroll
            for (int q = 0; q < 2; q++) {
                Ws[nb][bkh+q*4+0][brow] = (&rb[q].x)[0];
                Ws[nb][bkh+q*4+1][brow] = (&rb[q].x)[1];
                Ws[nb][bkh+q*4+2][brow] = (&rb[q].x)[2];
                Ws[nb][bkh+q*4+3][brow] = (&rb[q].x)[3];
            }
            __syncthreads();
        }
    }

    // epilogue: float4 stores with M guard per row
    #pragma unroll
    for (int i = 0; i < 8; i++) {
        int m = m0 + ty*8 + i;
        if (m >= M) continue;
        float* Cr = C + (size_t)m*ldc + n0 + tx*8;
        float4 v0 = make_float4(acc[i][0], acc[i][1], acc[i][2], acc[i][3]);
        float4 v1 = make_float4(acc[i][4], acc[i][5], acc[i][6], acc[i][7]);
        *(float4*)(Cr)     = v0;
        *(float4*)(Cr + 4) = v1;
    }
}

// ---------------- split-K reduce variants (P partial buffers) ----------------
template<int P>
__global__ void __launch_bounds__(256) reduce_res(const float* __restrict__ part,
                                                  float* __restrict__ h, int MN) {
    int i = blockIdx.x*256 + threadIdx.x;
    if (i < MN) {
        float v = 0.f;
        #pragma unroll
        for (int p = 0; p < P; p++) v += part[i + (size_t)p*MN];
        h[i] += v;
    }
}
template<int P>
__global__ void __launch_bounds__(256) reduce_relu(const float* __restrict__ part,
                                                   const float* __restrict__ bias,
                                                   float* __restrict__ outp, int MN, int ldn) {
    int i = blockIdx.x*256 + threadIdx.x;
    if (i < MN) {
        float v = bias[i % ldn];
        #pragma unroll
        for (int p = 0; p < P; p++) v += part[i + (size_t)p*MN];
        outp[i] = fmaxf(v, 0.f);
    }
}
template<int P>
__global__ void __launch_bounds__(256) reduce_bias(const float* __restrict__ part,
                                                   const float* __restrict__ bias,
                                                   float* __restrict__ outp, int MN, int ldn) {
    int i = blockIdx.x*256 + threadIdx.x;
    if (i < MN) {
        float v = bias[i % ldn];
        #pragma unroll
        for (int p = 0; p < P; p++) v += part[i + (size_t)p*MN];
        outp[i] = v;
    }
}
// patch: M=2048 rows x 384; scatter to h rows (skip cls), add bias + pos
template<int P>
__global__ void __launch_bounds__(256) reduce_patch(const float* __restrict__ part,
                                                    const float* __restrict__ bias,
                                                    const float* __restrict__ pos) {
    int i = blockIdx.x*256 + threadIdx.x;
    const int MN = 2048*DMODEL;
    if (i >= MN) return;
    int n = i % DMODEL;
    int m = i / DMODEL;
    float v = bias[n] + pos[(size_t)((m & 511) + 1)*DMODEL + n];
    #pragma unroll
    for (int p = 0; p < P; p++) v += part[i + (size_t)p*MN];
    int rout = m + (m >> 9) + 1;          // b*513 + 1 + t
    g_s.h[(size_t)rout*DMODEL + n] = v;
}

// ---------------- old generic NT GEMM (kept for xproj / dt) ----------------
enum { E_NONE=0, E_SP=3 };

template<int EPI, bool VEC, bool KSPLIT>
__global__ void __launch_bounds__(256)
gemm_nt(const float* __restrict__ A, int lda,
        const float* __restrict__ W, int ldw,
        const float* __restrict__ bias,
        float* __restrict__ C, int ldc,
        int M, int N, int K)
{
    constexpr int BM = 64, BN = 64, BK = 16;
    __shared__ float As[BK][BM+4];
    __shared__ float Ws[BK][BN+4];
    int tid = threadIdx.x;                 // 256
    int m0 = blockIdx.x*BM, n0 = blockIdx.y*BN;
    int kz0 = 0, kz1 = K;
    if (KSPLIT) {
        int klen = (K + gridDim.z - 1) / gridDim.z;
        kz0 = blockIdx.z * klen;
        kz1 = min(K, kz0 + klen);
        C += (size_t)blockIdx.z * (size_t)M * ldc;
    }
    float acc[4][4];
    #pragma unroll
    for (int i = 0; i < 4; i++)
        #pragma unroll
        for (int j = 0; j < 4; j++) acc[i][j] = 0.f;

    int lr  = tid >> 2;
    int lc4 = (tid & 3) * 4;
    int ty  = tid >> 4, tx = tid & 15;

    for (int k0 = kz0; k0 < kz1; k0 += BK) {
        int ma = m0 + lr;
        int na = n0 + lr;
        if (VEC) {
            float4 va = make_float4(0,0,0,0), vw = make_float4(0,0,0,0);
            if (ma < M && (k0+lc4) < kz1) va = *(const float4*)(A + (size_t)ma*lda + k0 + lc4);
            if (na < N && (k0+lc4) < kz1) vw = *(const float4*)(W + (size_t)na*ldw + k0 + lc4);
            As[lc4+0][lr]=va.x; As[lc4+1][lr]=va.y; As[lc4+2][lr]=va.z; As[lc4+3][lr]=va.w;
            Ws[lc4+0][lr]=vw.x; Ws[lc4+1][lr]=vw.y; Ws[lc4+2][lr]=vw.z; Ws[lc4+3][lr]=vw.w;
        } else {
            #pragma unroll
            for (int j = 0; j < 4; j++) {
                int k = k0 + lc4 + j;
                As[lc4+j][lr] = (ma < M && k < kz1) ? A[(size_t)ma*lda + k] : 0.f;
                Ws[lc4+j][lr] = (na < N && k < kz1) ? W[(size_t)na*ldw + k] : 0.f;
            }
        }
        __syncthreads();
        #pragma unroll
        for (int kk = 0; kk < BK; kk++) {
            float a[4], bb[4];
            #pragma unroll
            for (int i = 0; i < 4; i++) a[i]  = As[kk][ty*4 + i];
            #pragma unroll
            for (int j = 0; j < 4; j++) bb[j] = Ws[kk][tx*4 + j];
            #pragma unroll
            for (int i = 0; i < 4; i++)
                #pragma unroll
                for (int j = 0; j < 4; j++)
                    acc[i][j] = fmaf(a[i], bb[j], acc[i][j]);
        }
        __syncthreads();
    }

    #pragma unroll
    for (int i = 0; i < 4; i++) {
        int m = m0 + ty*4 + i;
        if (m >= M) continue;
        #pragma unroll
        for (int j = 0; j < 4; j++) {
            int n = n0 + tx*4 + j;
            if (n >= N) continue;
            float v = acc[i][j];
            if (EPI == E_SP) { v += bias[n]; v = (v > 15.f) ? v : log1pf(__expf(v)); }
            C[(size_t)m*ldc + n] = v;
        }
    }
}

// ---------------- causal depthwise conv1d (K=4) + silu ----------------
__global__ void __launch_bounds__(256) conv1d_kernel(const float* __restrict__ w,
                                                     const float* __restrict__ bias) {
    int idx = blockIdx.x*256 + threadIdx.x;
    if (idx >= NTOK*DI) return;
    int d  = idx % DI;
    int bt = idx / DI;
    int b  = bt / SEQL;
    int t  = bt - b*SEQL;
    float acc = bias[d];
    const float* w4 = w + (size_t)d*4;
    #pragma unroll
    for (int k = 0; k < 4; k++) {
        int tt = t - 3 + k;
        if (tt >= 0)
            acc = fmaf(w4[k], g_s.xz[(size_t)(b*SEQL + tt)*(2*DI) + d], acc);
    }
    g_s.xc[idx] = silu_f(acc);
}

// ---------------- split-K reduce for x_proj ----------------
__global__ void __launch_bounds__(256) reduce_xdbl_kernel() {
    int i = blockIdx.x*256 + threadIdx.x;
    if (i < NTOK*XD) {
        const int PS = NTOK*XD;
        g_s.xdbl[i] = (g_s.xdblp[i] + g_s.xdblp[i+PS])
                    + (g_s.xdblp[i+2*PS] + g_s.xdblp[i+3*PS]);
    }
}

// ---------------- selective scan: 3-pass blocked scan ----------------
__global__ void __launch_bounds__(128) scan_pass1(const float* __restrict__ Aoff) {
    int d = blockIdx.x*128 + threadIdx.x;
    int c = blockIdx.y, b = blockIdx.z;
    float s[NST], ap[NST], Av[NST];
    const float4* A4 = (const float4*)(Aoff + (size_t)d*NST);
    #pragma unroll
    for (int i = 0; i < 4; i++) {
        float4 v = A4[i];
        Av[4*i]=v.x; Av[4*i+1]=v.y; Av[4*i+2]=v.z; Av[4*i+3]=v.w;
    }
    #pragma unroll
    for (int n = 0; n < NST; n++) { s[n] = 0.f; ap[n] = 1.f; }
    int t0 = c*CLEN, t1 = min(t0 + CLEN, SEQL);
    for (int t = t0; t < t1; t++) {
        int bt = b*SEQL + t;
        float dtv = g_s.dt[(size_t)bt*DI + d];
        float xcv = g_s.xc[(size_t)bt*DI + d];
        float du  = dtv * xcv;
        const float4* Bp = (const float4*)(g_s.xdbl + (size_t)bt*XD + DTRC);
        float Bv[NST];
        #pragma unroll
        for (int i = 0; i < 4; i++) {
            float4 v = Bp[i];
            Bv[4*i]=v.x; Bv[4*i+1]=v.y; Bv[4*i+2]=v.z; Bv[4*i+3]=v.w;
        }
        #pragma unroll
        for (int n = 0; n < NST; n++) {
            float e = __expf(dtv * Av[n]);
            ap[n] *= e;
            s[n] = fmaf(e, s[n], du * Bv[n]);
        }
    }
    size_t base = (((size_t)b*NCH + c)*DI + d) * NST;
    float4* se  = (float4*)(g_s.send  + base);
    float4* apo = (float4*)(g_s.aprod + base);
    #pragma unroll
    for (int i = 0; i < 4; i++) {
        se[i]  = make_float4(s[4*i],  s[4*i+1],  s[4*i+2],  s[4*i+3]);
        apo[i] = make_float4(ap[4*i], ap[4*i+1], ap[4*i+2], ap[4*i+3]);
    }
}

__global__ void __launch_bounds__(256) scan_pass2() {
    int idx = blockIdx.x*256 + threadIdx.x;
    if (idx >= NB*DI*NST) return;
    int b  = idx / (DI*NST);
    int dn = idx - b*DI*NST;
    float s = 0.f;
    #pragma unroll
    for (int c = 0; c < NCH; c++) {
        size_t o = ((size_t)b*NCH + c)*DI*NST + dn;
        g_s.sinit[o] = s;
        s = fmaf(g_s.aprod[o], s, g_s.send[o]);
    }
}

__global__ void __launch_bounds__(128) scan_pass3(const float* __restrict__ Aoff,
                                                  const float* __restrict__ Dsk) {
    int d = blockIdx.x*128 + threadIdx.x;
    int c = blockIdx.y, b = blockIdx.z;
    float s[NST], Av[NST];
    const float4* A4 = (const float4*)(Aoff + (size_t)d*NST);
    #pragma unroll
    for (int i = 0; i < 4; i++) {
        float4 v = A4[i];
        Av[4*i]=v.x; Av[4*i+1]=v.y; Av[4*i+2]=v.z; Av[4*i+3]=v.w;
    }
    size_t base = (((size_t)b*NCH + c)*DI + d) * NST;
    const float4* si = (const float4*)(g_s.sinit + base);
    #pragma unroll
    for (int i = 0; i < 4; i++) {
        float4 v = si[i];
        s[4*i]=v.x; s[4*i+1]=v.y; s[4*i+2]=v.z; s[4*i+3]=v.w;
    }
    float Dv = Dsk[d];
    int t0 = c*CLEN, t1 = min(t0 + CLEN, SEQL);
    for (int t = t0; t < t1; t++) {
        int bt = b*SEQL + t;
        float dtv = g_s.dt[(size_t)bt*DI + d];
        float xcv = g_s.xc[(size_t)bt*DI + d];
        float du  = dtv * xcv;
        const float4* Bp = (const float4*)(g_s.xdbl + (size_t)bt*XD + DTRC);
        const float4* Cp = (const float4*)(g_s.xdbl + (size_t)bt*XD + DTRC + NST);
        float Bv[NST], Cv[NST];
        #pragma unroll
        for (int i = 0; i < 4; i++) {
            float4 v = Bp[i];
            Bv[4*i]=v.x; Bv[4*i+1]=v.y; Bv[4*i+2]=v.z; Bv[4*i+3]=v.w;
            float4 u = Cp[i];
            Cv[4*i]=u.x; Cv[4*i+1]=u.y; Cv[4*i+2]=u.z; Cv[4*i+3]=u.w;
        }
        float accy = 0.f;
        #pragma unroll
        for (int n = 0; n < NST; n++) {
            float e = __expf(dtv * Av[n]);
            s[n] = fmaf(e, s[n], du * Bv[n]);
            accy = fmaf(s[n], Cv[n], accy);
        }
        float zv = g_s.xz[(size_t)bt*(2*DI) + DI + d];
        g_s.y[(size_t)bt*DI + d] = (accy + Dv*xcv) * silu_f(zv);
    }
}

// ---------------- host launch ----------------
extern "C" void kernel_launch(void* const* d_in, const int* in_sizes, int n_in,
                              void* d_out, int out_size)
{
    (void)in_sizes; (void)n_in; (void)out_size;
    const float* x        = (const float*)d_in[0];
    const float* conv_w   = (const float*)d_in[1];
    const float* conv_b   = (const float*)d_in[2];
    const float* cls_tok  = (const float*)d_in[3];
    const float* pos      = (const float*)d_in[4];
    const float* norm_w   = (const float*)d_in[5];
    const float* norm_b   = (const float*)d_in[6];
    const float* in_proj  = (const float*)d_in[7];
    const float* c1w      = (const float*)d_in[8];
    const float* c1b      = (const float*)d_in[9];
    const float* xpw      = (const float*)d_in[10];
    const float* dtw      = (const float*)d_in[11];
    const float* dtb      = (const float*)d_in[12];
    const float* A_log    = (const float*)d_in[13];
    const float* D_skip   = (const float*)d_in[14];
    const float* opw      = (const float*)d_in[15];
    const float* normf_w  = (const float*)d_in[16];
    const float* normf_b  = (const float*)d_in[17];
    const float* hw1      = (const float*)d_in[18];
    const float* hb1      = (const float*)d_in[19];
    const float* hw2      = (const float*)d_in[20];
    const float* hb2      = (const float*)d_in[21];
    float* out = (float*)d_out;

    void* sp = nullptr;
    cudaGetSymbolAddress(&sp, g_s);
    Scratch* S = (Scratch*)sp;
    float* pPatch = S->patch;
    float* pH     = S->h;
    float* pHn    = S->hn;
    float* pXz    = S->xz;
    float* pXc    = S->xc;
    float* pXdbl  = S->xdbl;
    float* pXdblP = S->xdblp;
    float* pDt    = S->dt;
    float* pY     = S->y;
    float* pA     = S->A;
    float* pPart  = S->part;

    prep_A_kernel<<<(DEPTH*DI*NST + 255)/256, 256>>>(A_log);

    // patch embed: gemm2 splitK=4 (K=256 -> 64 each) + patch reduce (bias+pos+scatter)
    patch_reorder_kernel<<<(NB*1024*128 + 255)/256, 256>>>(x);
    cls_kernel<<<NB, DMODEL>>>(cls_tok, pos);
    gemm2<true><<<dim3(16, 6, 4), 128>>>(
        pPatch, 256, conv_w, 256, pPart, DMODEL, 2048, DMODEL, 256);
    reduce_patch<4><<<(2048*DMODEL + 255)/256, 256>>>(pPart, conv_b, pos);

    const int MT128 = (NTOK + 127)/128;   // 17
    const int MT64  = (NTOK + 63)/64;     // 33
    const int MNh   = NTOK*DMODEL;        // 788k

    for (int l = 0; l < DEPTH; l++) {
        const float* nw   = norm_w + (size_t)l*DMODEL;
        const float* nb   = norm_b + (size_t)l*DMODEL;
        const float* ipw  = in_proj + (size_t)l*2*DI*DMODEL;
        const float* cw   = c1w + (size_t)l*DI*4;
        const float* cb   = c1b + (size_t)l*DI;
        const float* xp   = xpw + (size_t)l*XD*DI;
        const float* dw   = dtw + (size_t)l*DI*DTRC;
        const float* db   = dtb + (size_t)l*DI;
        const float* Aoff = pA  + (size_t)l*DI*NST;
        const float* Dsk  = D_skip + (size_t)l*DI;
        const float* ow   = opw + (size_t)l*DMODEL*DI;

        ln_kernel<<<NTOK, 128>>>(pH, nw, nb, pHn);

        // xz = hn @ in_proj^T   (2052 x 1536, K=384): direct, grid 17x24=408
        gemm2<false><<<dim3(MT128, 24), 128>>>(
            pHn, DMODEL, ipw, DMODEL, pXz, 2*DI, NTOK, 2*DI, DMODEL);

        conv1d_kernel<<<(NTOK*DI + 255)/256, 256>>>(cw, cb);

        // xdbl = xc @ x_proj^T  (2052 x 56, K=768) old kernel splitK=4
        gemm_nt<E_NONE, true, true><<<dim3(MT64, 1, 4), 256>>>(
            pXc, DI, xp, DI, nullptr, pXdblP, XD, NTOK, XD, DI);
        reduce_xdbl_kernel<<<(NTOK*XD + 255)/256, 256>>>();

        // dt = softplus(xdbl[:, :24] @ dt_proj^T + dtb)  (2052 x 768, K=24)
        gemm_nt<E_SP, false, false><<<dim3(MT64, 12), 256>>>(
            pXdbl, XD, dw, DTRC, db, pDt, DI, NTOK, DI, DTRC);

        // selective scan (3-pass blocked)
        scan_pass1<<<dim3(DI/128, NCH, NB), 128>>>(Aoff);
        scan_pass2<<<(NB*DI*NST + 255)/256, 256>>>();
        scan_pass3<<<dim3(DI/128, NCH, NB), 128>>>(Aoff, Dsk);

        // h += y @ out_proj^T   (2052 x 384, K=768): splitK=4 -> grid 408
        gemm2<true><<<dim3(MT128, 6, 4), 128>>>(
            pY, DI, ow, DI, pPart, DMODEL, NTOK, DMODEL, DI);
        reduce_res<4><<<(MNh + 255)/256, 256>>>(pPart, pH, MNh);
    }

    // final LN + head
    ln_kernel<<<NTOK, 128>>>(pH, normf_w, normf_b, pHn);

    // h1 = relu(hn @ hw1^T + hb1)  (2052 x 384, K=384): splitK=4 -> grid 408
    gemm2<true><<<dim3(MT128, 6, 4), 128>>>(
        pHn, DMODEL, hw1, DMODEL, pPart, DMODEL, NTOK, DMODEL, DMODEL);
    reduce_relu<4><<<(MNh + 255)/256, 256>>>(pPart, hb1, pXc, MNh, DMODEL);

    // out = h1 @ hw2^T + hb2       (2052 x 256, K=384): splitK=4 -> grid 272
    gemm2<true><<<dim3(MT128, 4, 4), 128>>>(
        pXc, DMODEL, hw2, DMODEL, pPart, HEADD, NTOK, HEADD, DMODEL);
    reduce_bias<4><<<(NTOK*HEADD + 255)/256, 256>>>(pPart, hb2, out, NTOK*HEADD, HEADD);
}

// round 12
// speedup vs baseline: 1.5753x; 1.3925x over previous
#include <cuda_runtime.h>
#include <cuda_bf16.h>
#include <math.h>

// ---------------- problem constants ----------------
#define NB      4
#define SEQL    513
#define NTOK    (NB*SEQL)    // 2052
#define DMODEL  384
#define DI      768
#define NST     16
#define XD      56
#define DTRC    24
#define DEPTH   8
#define NCH     16
#define CLEN    33
#define HEADD   256

// ---------------- scratch ----------------
struct Scratch {
    float patch[2048*256];
    float h    [NTOK*DMODEL];
    float hn   [NTOK*DMODEL];
    float xz   [NTOK*2*DI];
    float xc   [NTOK*DI];
    float xdbl [NTOK*XD];
    float xdblp[4*NTOK*XD];
    float dt   [NTOK*DI];
    float y    [NTOK*DI];
    float A    [DEPTH*DI*NST];
    float send [NB*NCH*DI*NST];
    float aprod[NB*NCH*DI*NST];
    float sinit[NB*NCH*DI*NST];
    float part [2*NTOK*DMODEL];      // split-K partials (2 x 2052 x 384 max)
};
__device__ Scratch g_s;

__device__ __forceinline__ float silu_f(float x) {
    return x / (1.f + __expf(-x));
}

// ---------------- fp32 -> bf16 hi/lo split ----------------
__device__ __forceinline__ void cvt4(float4 v, uint2& hi, uint2& lo) {
    float f[4] = {v.x, v.y, v.z, v.w};
    unsigned hb[4], lb[4];
    #pragma unroll
    for (int i = 0; i < 4; i++) {
        __nv_bfloat16 h = __float2bfloat16_rn(f[i]);
        float lf = f[i] - __bfloat162float(h);
        __nv_bfloat16 l = __float2bfloat16_rn(lf);
        hb[i] = (unsigned)*(unsigned short*)&h;
        lb[i] = (unsigned)*(unsigned short*)&l;
    }
    hi.x = hb[0] | (hb[1] << 16); hi.y = hb[2] | (hb[3] << 16);
    lo.x = lb[0] | (lb[1] << 16); lo.y = lb[2] | (lb[3] << 16);
}

__device__ __forceinline__ void mma16816(float* c, const unsigned* a, unsigned b0, unsigned b1) {
    asm volatile(
        "mma.sync.aligned.m16n8k16.row.col.f32.bf16.bf16.f32 "
        "{%0,%1,%2,%3}, {%4,%5,%6,%7}, {%8,%9}, {%0,%1,%2,%3};"
        : "+f"(c[0]), "+f"(c[1]), "+f"(c[2]), "+f"(c[3])
        : "r"(a[0]), "r"(a[1]), "r"(a[2]), "r"(a[3]), "r"(b0), "r"(b1));
}

// ================= bf16-split HMMA GEMM: C[m,n] = sum_k A[m,k]*W[n,k] =================
// BM=128, BN=64, BK=32, 256 threads (8 warps: 4x2 of 32x32).
// K % 32 == 0 (per split), N % 64 == 0, M guarded.
// KSPLIT: gridDim.z splits K evenly; partial z writes to C + z*M*ldc.
template<bool KSPLIT>
__global__ void __launch_bounds__(256, 2)
gemm_mma(const float* __restrict__ A, int lda,
         const float* __restrict__ W, int ldw,
         float* __restrict__ C, int ldc,
         int M, int N, int K)
{
    __shared__ __nv_bfloat16 Ah[128][40];
    __shared__ __nv_bfloat16 Al[128][40];
    __shared__ __nv_bfloat16 Bh[64][40];
    __shared__ __nv_bfloat16 Bl[64][40];

    int tid = threadIdx.x;
    int wid = tid >> 5, lane = tid & 31;
    int wm = wid & 3;            // m: 4 warps x 32 rows
    int wn = wid >> 2;           // n: 2 warps x 32 cols
    int g = lane >> 2, t = lane & 3;
    int m0 = blockIdx.x * 128;
    int n0 = blockIdx.y * 64;

    int kz0 = 0, kiters = K >> 5;
    if (KSPLIT) {
        int klen = K / gridDim.z;        // multiple of 32 by construction
        kz0 = blockIdx.z * klen;
        kiters = klen >> 5;
        C += (size_t)blockIdx.z * (size_t)M * ldc;
    }

    float acc[2][4][4];
    #pragma unroll
    for (int mt = 0; mt < 2; mt++)
        #pragma unroll
        for (int nt = 0; nt < 4; nt++)
            #pragma unroll
            for (int q = 0; q < 4; q++) acc[mt][nt][q] = 0.f;

    for (int kc = 0; kc < kiters; kc++) {
        int k0 = kz0 + (kc << 5);
        if (kc > 0) __syncthreads();       // protect smem from previous compute
        // A tile: 128 rows x 32 k (1024 float4 groups, 4 per thread)
        #pragma unroll
        for (int it = 0; it < 4; it++) {
            int idx = it * 256 + tid;
            int row = idx >> 3, gr = idx & 7;
            int m = m0 + row;
            float4 v = (m < M) ? *(const float4*)(A + (size_t)m * lda + k0 + gr * 4)
                               : make_float4(0, 0, 0, 0);
            uint2 hi, lo;
            cvt4(v, hi, lo);
            *(uint2*)&Ah[row][gr * 4] = hi;
            *(uint2*)&Al[row][gr * 4] = lo;
        }
        // B tile: 64 rows x 32 k (512 groups, 2 per thread)
        #pragma unroll
        for (int it = 0; it < 2; it++) {
            int idx = it * 256 + tid;
            int row = idx >> 3, gr = idx & 7;
            float4 v = *(const float4*)(W + (size_t)(n0 + row) * ldw + k0 + gr * 4);
            uint2 hi, lo;
            cvt4(v, hi, lo);
            *(uint2*)&Bh[row][gr * 4] = hi;
            *(uint2*)&Bl[row][gr * 4] = lo;
        }
        __syncthreads();

        #pragma unroll
        for (int ks = 0; ks < 2; ks++) {
            int k16 = ks * 16;
            unsigned ah[2][4], al[2][4];
            #pragma unroll
            for (int mt = 0; mt < 2; mt++) {
                int r = wm * 32 + mt * 16 + g;
                ah[mt][0] = *(const unsigned*)&Ah[r    ][k16 + t*2];
                ah[mt][1] = *(const unsigned*)&Ah[r + 8][k16 + t*2];
                ah[mt][2] = *(const unsigned*)&Ah[r    ][k16 + t*2 + 8];
                ah[mt][3] = *(const unsigned*)&Ah[r + 8][k16 + t*2 + 8];
                al[mt][0] = *(const unsigned*)&Al[r    ][k16 + t*2];
                al[mt][1] = *(const unsigned*)&Al[r + 8][k16 + t*2];
                al[mt][2] = *(const unsigned*)&Al[r    ][k16 + t*2 + 8];
                al[mt][3] = *(const unsigned*)&Al[r + 8][k16 + t*2 + 8];
            }
            #pragma unroll
            for (int nt = 0; nt < 4; nt++) {
                int rn = wn * 32 + nt * 8 + g;
                unsigned bh0 = *(const unsigned*)&Bh[rn][k16 + t*2];
                unsigned bh1 = *(const unsigned*)&Bh[rn][k16 + t*2 + 8];
                unsigned bl0 = *(const unsigned*)&Bl[rn][k16 + t*2];
                unsigned bl1 = *(const unsigned*)&Bl[rn][k16 + t*2 + 8];
                #pragma unroll
                for (int mt = 0; mt < 2; mt++) {
                    mma16816(acc[mt][nt], ah[mt], bh0, bh1);
                    mma16816(acc[mt][nt], ah[mt], bl0, bl1);
                    mma16816(acc[mt][nt], al[mt], bh0, bh1);
                }
            }
        }
    }

    // epilogue: raw fp32 writes (fused ops happen in reduce kernels / direct consumers)
    #pragma unroll
    for (int mt = 0; mt < 2; mt++) {
        #pragma unroll
        for (int half = 0; half < 2; half++) {
            int r = m0 + wm * 32 + mt * 16 + g + half * 8;
            if (r >= M) continue;
            float* Cr = C + (size_t)r * ldc;
            #pragma unroll
            for (int nt = 0; nt < 4; nt++) {
                int cn = n0 + wn * 32 + nt * 8 + t * 2;
                float2 v = make_float2(acc[mt][nt][half*2 + 0], acc[mt][nt][half*2 + 1]);
                *(float2*)(Cr + cn) = v;
            }
        }
    }
}

// ---------------- split-K reduce variants (P=2) ----------------
template<int P>
__global__ void __launch_bounds__(256) reduce_res(const float* __restrict__ part,
                                                  float* __restrict__ h, int MN) {
    int i = blockIdx.x*256 + threadIdx.x;
    if (i < MN) {
        float v = 0.f;
        #pragma unroll
        for (int p = 0; p < P; p++) v += part[i + (size_t)p*MN];
        h[i] += v;
    }
}
template<int P>
__global__ void __launch_bounds__(256) reduce_relu(const float* __restrict__ part,
                                                   const float* __restrict__ bias,
                                                   float* __restrict__ outp, int MN, int ldn) {
    int i = blockIdx.x*256 + threadIdx.x;
    if (i < MN) {
        float v = bias[i % ldn];
        #pragma unroll
        for (int p = 0; p < P; p++) v += part[i + (size_t)p*MN];
        outp[i] = fmaxf(v, 0.f);
    }
}
template<int P>
__global__ void __launch_bounds__(256) reduce_bias(const float* __restrict__ part,
                                                   const float* __restrict__ bias,
                                                   float* __restrict__ outp, int MN, int ldn) {
    int i = blockIdx.x*256 + threadIdx.x;
    if (i < MN) {
        float v = bias[i % ldn];
        #pragma unroll
        for (int p = 0; p < P; p++) v += part[i + (size_t)p*MN];
        outp[i] = v;
    }
}
template<int P>
__global__ void __launch_bounds__(256) reduce_patch(const float* __restrict__ part,
                                                    const float* __restrict__ bias,
                                                    const float* __restrict__ pos) {
    int i = blockIdx.x*256 + threadIdx.x;
    const int MN = 2048*DMODEL;
    if (i >= MN) return;
    int n = i % DMODEL;
    int m = i / DMODEL;
    float v = bias[n] + pos[(size_t)((m & 511) + 1)*DMODEL + n];
    #pragma unroll
    for (int p = 0; p < P; p++) v += part[i + (size_t)p*MN];
    int rout = m + (m >> 9) + 1;          // b*513 + 1 + t
    g_s.h[(size_t)rout*DMODEL + n] = v;
}

// ---------------- misc kernels ----------------
__global__ void __launch_bounds__(256) prep_A_kernel(const float* __restrict__ Alog) {
    int i = blockIdx.x*256 + threadIdx.x;
    if (i < DEPTH*DI*NST) g_s.A[i] = -__expf(Alog[i]);
}

__global__ void __launch_bounds__(256) patch_reorder_kernel(const float* __restrict__ x) {
    int idx = blockIdx.x*256 + threadIdx.x;
    if (idx >= NB*1024*128) return;
    int f = idx & 127;
    int r = (idx >> 7) & 1023;
    int b = idx >> 17;
    g_s.patch[(((size_t)b*512 + (r>>1)) << 8) + f*2 + (r & 1)] = x[idx];
}

__global__ void __launch_bounds__(384) cls_kernel(const float* __restrict__ cls,
                                                  const float* __restrict__ pos) {
    int b = blockIdx.x;
    int d = threadIdx.x;
    g_s.h[(size_t)b*SEQL*DMODEL + d] = cls[d] + pos[d];
}

__global__ void __launch_bounds__(128) ln_kernel(const float* __restrict__ in,
                          const float* __restrict__ w,
                          const float* __restrict__ bv,
                          float* __restrict__ out) {
    int row = blockIdx.x;
    int tid = threadIdx.x;
    const float* x = in + (size_t)row*DMODEL;
    float v0 = x[tid], v1 = x[tid+128], v2 = x[tid+256];
    float s = v0+v1+v2;
    float q = v0*v0 + v1*v1 + v2*v2;
    #pragma unroll
    for (int o = 16; o > 0; o >>= 1) {
        s += __shfl_xor_sync(0xFFFFFFFFu, s, o);
        q += __shfl_xor_sync(0xFFFFFFFFu, q, o);
    }
    __shared__ float ss[4], qq[4];
    if ((tid & 31) == 0) { ss[tid>>5] = s; qq[tid>>5] = q; }
    __syncthreads();
    s = ss[0]+ss[1]+ss[2]+ss[3];
    q = qq[0]+qq[1]+qq[2]+qq[3];
    float mean = s * (1.f/384.f);
    float var  = q * (1.f/384.f) - mean*mean;
    float inv  = rsqrtf(var + 1e-5f);
    float* o = out + (size_t)row*DMODEL;
    o[tid]     = (v0-mean)*inv*w[tid]     + bv[tid];
    o[tid+128] = (v1-mean)*inv*w[tid+128] + bv[tid+128];
    o[tid+256] = (v2-mean)*inv*w[tid+256] + bv[tid+256];
}

enum { E_NONE=0, E_SP=3 };

template<int EPI, bool VEC, bool KSPLIT>
__global__ void __launch_bounds__(256)
gemm_nt(const float* __restrict__ A, int lda,
        const float* __restrict__ W, int ldw,
        const float* __restrict__ bias,
        float* __restrict__ C, int ldc,
        int M, int N, int K)
{
    constexpr int BM = 64, BN = 64, BK = 16;
    __shared__ float As[BK][BM+4];
    __shared__ float Ws[BK][BN+4];
    int tid = threadIdx.x;
    int m0 = blockIdx.x*BM, n0 = blockIdx.y*BN;
    int kz0 = 0, kz1 = K;
    if (KSPLIT) {
        int klen = (K + gridDim.z - 1) / gridDim.z;
        kz0 = blockIdx.z * klen;
        kz1 = min(K, kz0 + klen);
        C += (size_t)blockIdx.z * (size_t)M * ldc;
    }
    float acc[4][4];
    #pragma unroll
    for (int i = 0; i < 4; i++)
        #pragma unroll
        for (int j = 0; j < 4; j++) acc[i][j] = 0.f;

    int lr  = tid >> 2;
    int lc4 = (tid & 3) * 4;
    int ty  = tid >> 4, tx = tid & 15;

    for (int k0 = kz0; k0 < kz1; k0 += BK) {
        int ma = m0 + lr;
        int na = n0 + lr;
        if (VEC) {
            float4 va = make_float4(0,0,0,0), vw = make_float4(0,0,0,0);
            if (ma < M && (k0+lc4) < kz1) va = *(const float4*)(A + (size_t)ma*lda + k0 + lc4);
            if (na < N && (k0+lc4) < kz1) vw = *(const float4*)(W + (size_t)na*ldw + k0 + lc4);
            As[lc4+0][lr]=va.x; As[lc4+1][lr]=va.y; As[lc4+2][lr]=va.z; As[lc4+3][lr]=va.w;
            Ws[lc4+0][lr]=vw.x; Ws[lc4+1][lr]=vw.y; Ws[lc4+2][lr]=vw.z; Ws[lc4+3][lr]=vw.w;
        } else {
            #pragma unroll
            for (int j = 0; j < 4; j++) {
                int k = k0 + lc4 + j;
                As[lc4+j][lr] = (ma < M && k < kz1) ? A[(size_t)ma*lda + k] : 0.f;
                Ws[lc4+j][lr] = (na < N && k < kz1) ? W[(size_t)na*ldw + k] : 0.f;
            }
        }
        __syncthreads();
        #pragma unroll
        for (int kk = 0; kk < BK; kk++) {
            float a[4], bb[4];
            #pragma unroll
            for (int i = 0; i < 4; i++) a[i]  = As[kk][ty*4 + i];
            #pragma unroll
            for (int j = 0; j < 4; j++) bb[j] = Ws[kk][tx*4 + j];
            #pragma unroll
            for (int i = 0; i < 4; i++)
                #pragma unroll
                for (int j = 0; j < 4; j++)
                    acc[i][j] = fmaf(a[i], bb[j], acc[i][j]);
        }
        __syncthreads();
    }

    #pragma unroll
    for (int i = 0; i < 4; i++) {
        int m = m0 + ty*4 + i;
        if (m >= M) continue;
        #pragma unroll
        for (int j = 0; j < 4; j++) {
            int n = n0 + tx*4 + j;
            if (n >= N) continue;
            float v = acc[i][j];
            if (EPI == E_SP) { v += bias[n]; v = (v > 15.f) ? v : log1pf(__expf(v)); }
            C[(size_t)m*ldc + n] = v;
        }
    }
}

__global__ void __launch_bounds__(256) conv1d_kernel(const float* __restrict__ w,
                                                     const float* __restrict__ bias) {
    int idx = blockIdx.x*256 + threadIdx.x;
    if (idx >= NTOK*DI) return;
    int d  = idx % DI;
    int bt = idx / DI;
    int b  = bt / SEQL;
    int t  = bt - b*SEQL;
    float acc = bias[d];
    const float* w4 = w + (size_t)d*4;
    #pragma unroll
    for (int k = 0; k < 4; k++) {
        int tt = t - 3 + k;
        if (tt >= 0)
            acc = fmaf(w4[k], g_s.xz[(size_t)(b*SEQL + tt)*(2*DI) + d], acc);
    }
    g_s.xc[idx] = silu_f(acc);
}

__global__ void __launch_bounds__(256) reduce_xdbl_kernel() {
    int i = blockIdx.x*256 + threadIdx.x;
    if (i < NTOK*XD) {
        const int PS = NTOK*XD;
        g_s.xdbl[i] = (g_s.xdblp[i] + g_s.xdblp[i+PS])
                    + (g_s.xdblp[i+2*PS] + g_s.xdblp[i+3*PS]);
    }
}

__global__ void __launch_bounds__(128) scan_pass1(const float* __restrict__ Aoff) {
    int d = blockIdx.x*128 + threadIdx.x;
    int c = blockIdx.y, b = blockIdx.z;
    float s[NST], ap[NST], Av[NST];
    const float4* A4 = (const float4*)(Aoff + (size_t)d*NST);
    #pragma unroll
    for (int i = 0; i < 4; i++) {
        float4 v = A4[i];
        Av[4*i]=v.x; Av[4*i+1]=v.y; Av[4*i+2]=v.z; Av[4*i+3]=v.w;
    }
    #pragma unroll
    for (int n = 0; n < NST; n++) { s[n] = 0.f; ap[n] = 1.f; }
    int t0 = c*CLEN, t1 = min(t0 + CLEN, SEQL);
    for (int t = t0; t < t1; t++) {
        int bt = b*SEQL + t;
        float dtv = g_s.dt[(size_t)bt*DI + d];
        float xcv = g_s.xc[(size_t)bt*DI + d];
        float du  = dtv * xcv;
        const float4* Bp = (const float4*)(g_s.xdbl + (size_t)bt*XD + DTRC);
        float Bv[NST];
        #pragma unroll
        for (int i = 0; i < 4; i++) {
            float4 v = Bp[i];
            Bv[4*i]=v.x; Bv[4*i+1]=v.y; Bv[4*i+2]=v.z; Bv[4*i+3]=v.w;
        }
        #pragma unroll
        for (int n = 0; n < NST; n++) {
            float e = __expf(dtv * Av[n]);
            ap[n] *= e;
            s[n] = fmaf(e, s[n], du * Bv[n]);
        }
    }
    size_t base = (((size_t)b*NCH + c)*DI + d) * NST;
    float4* se  = (float4*)(g_s.send  + base);
    float4* apo = (float4*)(g_s.aprod + base);
    #pragma unroll
    for (int i = 0; i < 4; i++) {
        se[i]  = make_float4(s[4*i],  s[4*i+1],  s[4*i+2],  s[4*i+3]);
        apo[i] = make_float4(ap[4*i], ap[4*i+1], ap[4*i+2], ap[4*i+3]);
    }
}

__global__ void __launch_bounds__(256) scan_pass2() {
    int idx = blockIdx.x*256 + threadIdx.x;
    if (idx >= NB*DI*NST) return;
    int b  = idx / (DI*NST);
    int dn = idx - b*DI*NST;
    float s = 0.f;
    #pragma unroll
    for (int c = 0; c < NCH; c++) {
        size_t o = ((size_t)b*NCH + c)*DI*NST + dn;
        g_s.sinit[o] = s;
        s = fmaf(g_s.aprod[o], s, g_s.send[o]);
    }
}

__global__ void __launch_bounds__(128) scan_pass3(const float* __restrict__ Aoff,
                                                  const float* __restrict__ Dsk) {
    int d = blockIdx.x*128 + threadIdx.x;
    int c = blockIdx.y, b = blockIdx.z;
    float s[NST], Av[NST];
    const float4* A4 = (const float4*)(Aoff + (size_t)d*NST);
    #pragma unroll
    for (int i = 0; i < 4; i++) {
        float4 v = A4[i];
        Av[4*i]=v.x; Av[4*i+1]=v.y; Av[4*i+2]=v.z; Av[4*i+3]=v.w;
    }
    size_t base = (((size_t)b*NCH + c)*DI + d) * NST;
    const float4* si = (const float4*)(g_s.sinit + base);
    #pragma unroll
    for (int i = 0; i < 4; i++) {
        float4 v = si[i];
        s[4*i]=v.x; s[4*i+1]=v.y; s[4*i+2]=v.z; s[4*i+3]=v.w;
    }
    float Dv = Dsk[d];
    int t0 = c*CLEN, t1 = min(t0 + CLEN, SEQL);
    for (int t = t0; t < t1; t++) {
        int bt = b*SEQL + t;
        float dtv = g_s.dt[(size_t)bt*DI + d];
        float xcv = g_s.xc[(size_t)bt*DI + d];
        float du  = dtv * xcv;
        const float4* Bp = (const float4*)(g_s.xdbl + (size_t)bt*XD + DTRC);
        const float4* Cp = (const float4*)(g_s.xdbl + (size_t)bt*XD + DTRC + NST);
        float Bv[NST], Cv[NST];
        #pragma unroll
        for (int i = 0; i < 4; i++) {
            float4 v = Bp[i];
            Bv[4*i]=v.x; Bv[4*i+1]=v.y; Bv[4*i+2]=v.z; Bv[4*i+3]=v.w;
            float4 u = Cp[i];
            Cv[4*i]=u.x; Cv[4*i+1]=u.y; Cv[4*i+2]=u.z; Cv[4*i+3]=u.w;
        }
        float accy = 0.f;
        #pragma unroll
        for (int n = 0; n < NST; n++) {
            float e = __expf(dtv * Av[n]);
            s[n] = fmaf(e, s[n], du * Bv[n]);
            accy = fmaf(s[n], Cv[n], accy);
        }
        float zv = g_s.xz[(size_t)bt*(2*DI) + DI + d];
        g_s.y[(size_t)bt*DI + d] = (accy + Dv*xcv) * silu_f(zv);
    }
}

// ---------------- host launch ----------------
extern "C" void kernel_launch(void* const* d_in, const int* in_sizes, int n_in,
                              void* d_out, int out_size)
{
    (void)in_sizes; (void)n_in; (void)out_size;
    const float* x        = (const float*)d_in[0];
    const float* conv_w   = (const float*)d_in[1];
    const float* conv_b   = (const float*)d_in[2];
    const float* cls_tok  = (const float*)d_in[3];
    const float* pos      = (const float*)d_in[4];
    const float* norm_w   = (const float*)d_in[5];
    const float* norm_b   = (const float*)d_in[6];
    const float* in_proj  = (const float*)d_in[7];
    const float* c1w      = (const float*)d_in[8];
    const float* c1b      = (const float*)d_in[9];
    const float* xpw      = (const float*)d_in[10];
    const float* dtw      = (const float*)d_in[11];
    const float* dtb      = (const float*)d_in[12];
    const float* A_log    = (const float*)d_in[13];
    const float* D_skip   = (const float*)d_in[14];
    const float* opw      = (const float*)d_in[15];
    const float* normf_w  = (const float*)d_in[16];
    const float* normf_b  = (const float*)d_in[17];
    const float* hw1      = (const float*)d_in[18];
    const float* hb1      = (const float*)d_in[19];
    const float* hw2      = (const float*)d_in[20];
    const float* hb2      = (const float*)d_in[21];
    float* out = (float*)d_out;

    void* sp = nullptr;
    cudaGetSymbolAddress(&sp, g_s);
    Scratch* S = (Scratch*)sp;
    float* pPatch = S->patch;
    float* pH     = S->h;
    float* pHn    = S->hn;
    float* pXz    = S->xz;
    float* pXc    = S->xc;
    float* pXdbl  = S->xdbl;
    float* pXdblP = S->xdblp;
    float* pDt    = S->dt;
    float* pY     = S->y;
    float* pA     = S->A;
    float* pPart  = S->part;

    prep_A_kernel<<<(DEPTH*DI*NST + 255)/256, 256>>>(A_log);

    // patch embed: HMMA GEMM (2048 x 384, K=256) splitK=2 + fused reduce
    patch_reorder_kernel<<<(NB*1024*128 + 255)/256, 256>>>(x);
    cls_kernel<<<NB, DMODEL>>>(cls_tok, pos);
    gemm_mma<true><<<dim3(16, 6, 2), 256>>>(
        pPatch, 256, conv_w, 256, pPart, DMODEL, 2048, DMODEL, 256);
    reduce_patch<2><<<(2048*DMODEL + 255)/256, 256>>>(pPart, conv_b, pos);

    const int MT128 = (NTOK + 127)/128;   // 17
    const int MT64  = (NTOK + 63)/64;     // 33
    const int MNh   = NTOK*DMODEL;        // 788k

    for (int l = 0; l < DEPTH; l++) {
        const float* nw   = norm_w + (size_t)l*DMODEL;
        const float* nb   = norm_b + (size_t)l*DMODEL;
        const float* ipw  = in_proj + (size_t)l*2*DI*DMODEL;
        const float* cw   = c1w + (size_t)l*DI*4;
        const float* cb   = c1b + (size_t)l*DI;
        const float* xp   = xpw + (size_t)l*XD*DI;
        const float* dw   = dtw + (size_t)l*DI*DTRC;
        const float* db   = dtb + (size_t)l*DI;
        const float* Aoff = pA  + (size_t)l*DI*NST;
        const float* Dsk  = D_skip + (size_t)l*DI;
        const float* ow   = opw + (size_t)l*DMODEL*DI;

        ln_kernel<<<NTOK, 128>>>(pH, nw, nb, pHn);

        // xz = hn @ in_proj^T   (2052 x 1536, K=384): direct, grid 17x24=408
        gemm_mma<false><<<dim3(MT128, 24), 256>>>(
            pHn, DMODEL, ipw, DMODEL, pXz, 2*DI, NTOK, 2*DI, DMODEL);

        conv1d_kernel<<<(NTOK*DI + 255)/256, 256>>>(cw, cb);

        // xdbl = xc @ x_proj^T  (2052 x 56, K=768) simt splitK=4
        gemm_nt<E_NONE, true, true><<<dim3(MT64, 1, 4), 256>>>(
            pXc, DI, xp, DI, nullptr, pXdblP, XD, NTOK, XD, DI);
        reduce_xdbl_kernel<<<(NTOK*XD + 255)/256, 256>>>();

        // dt = softplus(xdbl[:, :24] @ dt_proj^T + dtb)
        gemm_nt<E_SP, false, false><<<dim3(MT64, 12), 256>>>(
            pXdbl, XD, dw, DTRC, db, pDt, DI, NTOK, DI, DTRC);

        // selective scan (3-pass blocked)
        scan_pass1<<<dim3(DI/128, NCH, NB), 128>>>(Aoff);
        scan_pass2<<<(NB*DI*NST + 255)/256, 256>>>();
        scan_pass3<<<dim3(DI/128, NCH, NB), 128>>>(Aoff, Dsk);

        // h += y @ out_proj^T   (2052 x 384, K=768): splitK=2 + residual reduce
        gemm_mma<true><<<dim3(MT128, 6, 2), 256>>>(
            pY, DI, ow, DI, pPart, DMODEL, NTOK, DMODEL, DI);
        reduce_res<2><<<(MNh + 255)/256, 256>>>(pPart, pH, MNh);
    }

    // final LN + head
    ln_kernel<<<NTOK, 128>>>(pH, normf_w, normf_b, pHn);

    // h1 = relu(hn @ hw1^T + hb1): splitK=2 + relu reduce
    gemm_mma<true><<<dim3(MT128, 6, 2), 256>>>(
        pHn, DMODEL, hw1, DMODEL, pPart, DMODEL, NTOK, DMODEL, DMODEL);
    reduce_relu<2><<<(MNh + 255)/256, 256>>>(pPart, hb1, pXc, MNh, DMODEL);

    // out = h1 @ hw2^T + hb2: splitK=2 + bias reduce
    gemm_mma<true><<<dim3(MT128, 4, 2), 256>>>(
        pXc, DMODEL, hw2, DMODEL, pPart, HEADD, NTOK, HEADD, DMODEL);
    reduce_bias<2><<<(NTOK*HEADD + 255)/256, 256>>>(pPart, hb2, out, NTOK*HEADD, HEADD);
}